// round 2
// baseline (speedup 1.0000x reference)
#include <cuda_runtime.h>
#include <math.h>

#define NN     2048
#define NFEAT  512
#define NHID   128
#define NHEADS 4
#define NP     3
#define PH     (NP*NHEADS)
#define ALPHA  0.2f

// ---------------- scratch (device globals: no allocation allowed) ----------------
__device__ float g_h [PH * NN * NHID];           // 12.6 MB  h[p][head][n][d]
__device__ float g_m [NP * NN * (NHEADS*NHID)];  // 12.6 MB  m[p][n][head*128+d]
__device__ float g_sv [PH * NN];
__device__ float g_Es [PH * NN];
__device__ float g_Eas[PH * NN];
__device__ float g_dv [PH * NN];
__device__ float g_Ed [PH * NN];
__device__ float g_Ead[PH * NN];
__device__ float g_scores[NP];

// ---------------- k0: zero the score accumulators ----------------
__global__ void k0_init() {
    if (threadIdx.x < NP) g_scores[threadIdx.x] = 0.f;
}

// ---------------- k1: h[ph] = x @ W_node[ph]   (2048x512x128 per ph) ----------------
__global__ __launch_bounds__(256) void k1_node_gemm(const float* __restrict__ x,
                                                    const float* __restrict__ Wn) {
    __shared__ float xs[64][33];
    __shared__ float ws[32 * 128];
    int ph   = blockIdx.y;
    int row0 = blockIdx.x * 64;
    const float* W = Wn + (size_t)ph * NFEAT * NHID;
    int tid = threadIdx.x;
    int rg = tid >> 4;   // 16 row groups  -> rows rg*4..+4
    int cg = tid & 15;   // 16 col groups  -> cols cg*8..+8

    float acc[4][8];
#pragma unroll
    for (int r = 0; r < 4; r++)
#pragma unroll
        for (int c = 0; c < 8; c++) acc[r][c] = 0.f;

    for (int k0 = 0; k0 < NFEAT; k0 += 32) {
        for (int i = tid; i < 64 * 32; i += 256)
            xs[i >> 5][i & 31] = x[(size_t)(row0 + (i >> 5)) * NFEAT + k0 + (i & 31)];
        for (int i = tid * 4; i < 32 * 128; i += 1024)
            *(float4*)&ws[i] = *(const float4*)&W[(size_t)k0 * 128 + i];
        __syncthreads();
#pragma unroll
        for (int k = 0; k < 32; k++) {
            float xv[4];
#pragma unroll
            for (int r = 0; r < 4; r++) xv[r] = xs[rg * 4 + r][k];
            float4 w0 = *(float4*)&ws[k * 128 + cg * 8];
            float4 w1 = *(float4*)&ws[k * 128 + cg * 8 + 4];
            float wv[8] = {w0.x, w0.y, w0.z, w0.w, w1.x, w1.y, w1.z, w1.w};
#pragma unroll
            for (int r = 0; r < 4; r++)
#pragma unroll
                for (int c = 0; c < 8; c++) acc[r][c] += xv[r] * wv[c];
        }
        __syncthreads();
    }
    float* hd = g_h + (size_t)ph * NN * NHID;
#pragma unroll
    for (int r = 0; r < 4; r++) {
        float* dst = hd + (size_t)(row0 + rg * 4 + r) * NHID + cg * 8;
        *(float4*)dst       = make_float4(acc[r][0], acc[r][1], acc[r][2], acc[r][3]);
        *(float4*)(dst + 4) = make_float4(acc[r][4], acc[r][5], acc[r][6], acc[r][7]);
    }
}

// ---------------- k2: s,d dots + the 4 exp vectors (factorized leakyrelu-exp) ----------------
__global__ __launch_bounds__(256) void k2_sd(const float* __restrict__ an) {
    int gw   = blockIdx.x * 8 + (threadIdx.x >> 5);   // one warp per (ph, n)
    int lane = threadIdx.x & 31;
    int ph = gw >> 11;
    int n  = gw & 2047;
    const float* hrow = g_h + ((size_t)ph * NN + n) * NHID;
    const float* a    = an + (size_t)ph * 2 * NHID;
    float s = 0.f, d = 0.f;
#pragma unroll
    for (int i = lane; i < NHID; i += 32) {
        float hv = hrow[i];
        s += hv * a[i];
        d += hv * a[NHID + i];
    }
#pragma unroll
    for (int off = 16; off; off >>= 1) {
        s += __shfl_xor_sync(0xffffffffu, s, off);
        d += __shfl_xor_sync(0xffffffffu, d, off);
    }
    if (lane == 0) {
        int idx = ph * NN + n;
        g_sv[idx] = s; g_Es[idx] = expf(s); g_Eas[idx] = expf(ALPHA * s);
        g_dv[idx] = d; g_Ed[idx] = expf(d); g_Ead[idx] = expf(ALPHA * d);
    }
}

// ---------------- k3: fused masked attention + (num @ h) + softmax-div + elu ----------------
// block: 128 threads, 64 rows x 128 dims output tile; loop m in chunks of 32.
__global__ __launch_bounds__(128) void k3_attn(const float* __restrict__ adjs) {
    __shared__ float s_sh[64], Es_sh[64], Eas_sh[64];
    __shared__ float dv_sh[32], Ed_sh[32], Ead_sh[32];
    __shared__ float adj_sh[64][33];   // padded: conflict-free column reads
    __shared__ float num[32][64];      // m-major for vectorized FMA-phase reads
    __shared__ float hs[32 * 128];
    __shared__ float rowpart[2][64];

    int ph   = blockIdx.y;
    int p    = ph >> 2, head = ph & 3;
    int row0 = blockIdx.x * 64;
    int tid  = threadIdx.x;

    if (tid < 64) {
        int idx = ph * NN + row0 + tid;
        s_sh[tid] = g_sv[idx]; Es_sh[tid] = g_Es[idx]; Eas_sh[tid] = g_Eas[idx];
    }
    int rg = tid >> 4;        // 8 row groups  -> rows rg*8..+8
    int cg = tid & 15;        // 16 col groups -> cols cg*8..+8
    int half = tid >> 6;      // num-phase: 2 threads per row
    int nn   = tid & 63;

    const float* adjbase = adjs + (size_t)p * NN * NN;
    const float* hbase   = g_h + (size_t)ph * NN * NHID;

    float acc[8][8];
#pragma unroll
    for (int r = 0; r < 8; r++)
#pragma unroll
        for (int c = 0; c < 8; c++) acc[r][c] = 0.f;
    float myrowsum = 0.f;

    for (int m0 = 0; m0 < NN; m0 += 32) {
        if (tid < 32) {
            int idx = ph * NN + m0 + tid;
            dv_sh[tid] = g_dv[idx]; Ed_sh[tid] = g_Ed[idx]; Ead_sh[tid] = g_Ead[idx];
        }
        const float* hsrc = hbase + (size_t)m0 * NHID;
#pragma unroll
        for (int i = tid * 4; i < 32 * 128; i += 512)
            *(float4*)&hs[i] = *(const float4*)&hsrc[i];
        // coalesced adj tile load (rows of 32 floats)
#pragma unroll
        for (int i = tid; i < 64 * 32; i += 128)
            adj_sh[i >> 5][i & 31] = adjbase[(size_t)(row0 + (i >> 5)) * NN + m0 + (i & 31)];
        __syncthreads();

        // ---- numerator phase: no exp, just select of precomputed products ----
        {
            float svv = s_sh[nn], Esv = Es_sh[nn], Easv = Eas_sh[nn];
            int mb = half * 16;
            float lsum = 0.f;
#pragma unroll
            for (int j = 0; j < 16; j++) {
                int mm = mb + j;
                float t = svv + dv_sh[mm];
                float w = (t > 0.f) ? (Esv * Ed_sh[mm]) : (Easv * Ead_sh[mm]);
                float v = (adj_sh[nn][mm] > 0.f) ? w : 0.f;
                num[mm][nn] = v;
                lsum += v;
            }
            myrowsum += lsum;
        }
        __syncthreads();

        // ---- FMA phase: acc += num^T-tile outer products with h tile ----
#pragma unroll
        for (int mm = 0; mm < 32; mm++) {
            float4 a0 = *(float4*)&num[mm][rg * 8];
            float4 a1 = *(float4*)&num[mm][rg * 8 + 4];
            float4 b0 = *(float4*)&hs[mm * 128 + cg * 8];
            float4 b1 = *(float4*)&hs[mm * 128 + cg * 8 + 4];
            float av[8] = {a0.x, a0.y, a0.z, a0.w, a1.x, a1.y, a1.z, a1.w};
            float bv[8] = {b0.x, b0.y, b0.z, b0.w, b1.x, b1.y, b1.z, b1.w};
#pragma unroll
            for (int r = 0; r < 8; r++)
#pragma unroll
                for (int c = 0; c < 8; c++) acc[r][c] += av[r] * bv[c];
        }
        __syncthreads();
    }

    rowpart[half][nn] = myrowsum;
    __syncthreads();

    float* mdst = g_m + ((size_t)p * NN + row0) * (NHEADS * NHID) + head * NHID;
#pragma unroll
    for (int r = 0; r < 8; r++) {
        int n = rg * 8 + r;
        float rs  = rowpart[0][n] + rowpart[1][n];
        float inv = (rs > 0.f) ? (1.f / rs) : 0.f;
        float v[8];
#pragma unroll
        for (int c = 0; c < 8; c++) {
            float t = acc[r][c] * inv;
            v[c] = (t > 0.f) ? t : expm1f(t);   // elu
        }
        float* dst = mdst + (size_t)n * (NHEADS * NHID) + cg * 8;
        *(float4*)dst       = make_float4(v[0], v[1], v[2], v[3]);
        *(float4*)(dst + 4) = make_float4(v[4], v[5], v[6], v[7]);
    }
}

// ---------------- k4: semantic attention scores (tanh(m@W+b)·q, summed per p) ----------------
__global__ __launch_bounds__(256) void k4_sem(const float* __restrict__ Wsem,
                                              const float* __restrict__ bsem,
                                              const float* __restrict__ qsem) {
    __shared__ float msh[32][65];
    __shared__ float wsh[64 * 128];
    __shared__ float red[8];
    int row0 = blockIdx.x * 32;        // rows of flat (p*n); 2048%32==0 -> single p per block
    int pidx = row0 / NN;
    int tid = threadIdx.x;
    int rg = tid >> 5;                  // 8 row groups -> rows rg*4..+4
    int cg = tid & 31;                  // 32 col groups -> cols cg*4..+4

    float acc[4][4];
#pragma unroll
    for (int r = 0; r < 4; r++)
#pragma unroll
        for (int c = 0; c < 4; c++) acc[r][c] = 0.f;

    for (int k0 = 0; k0 < 512; k0 += 64) {
        for (int i = tid; i < 32 * 64; i += 256)
            msh[i >> 6][i & 63] = g_m[(size_t)(row0 + (i >> 6)) * 512 + k0 + (i & 63)];
        for (int i = tid * 4; i < 64 * 128; i += 1024)
            *(float4*)&wsh[i] = *(const float4*)&Wsem[(size_t)k0 * 128 + i];
        __syncthreads();
#pragma unroll
        for (int k = 0; k < 64; k++) {
            float mv[4];
#pragma unroll
            for (int r = 0; r < 4; r++) mv[r] = msh[rg * 4 + r][k];
            float4 wv = *(float4*)&wsh[k * 128 + cg * 4];
            float wva[4] = {wv.x, wv.y, wv.z, wv.w};
#pragma unroll
            for (int r = 0; r < 4; r++)
#pragma unroll
                for (int c = 0; c < 4; c++) acc[r][c] += mv[r] * wva[c];
        }
        __syncthreads();
    }
    float part = 0.f;
#pragma unroll
    for (int c = 0; c < 4; c++) {
        int col = cg * 4 + c;
        float b = bsem[col], q = qsem[col];
#pragma unroll
        for (int r = 0; r < 4; r++)
            part += tanhf(acc[r][c] + b) * q;
    }
#pragma unroll
    for (int off = 16; off; off >>= 1)
        part += __shfl_xor_sync(0xffffffffu, part, off);
    if ((tid & 31) == 0) red[tid >> 5] = part;
    __syncthreads();
    if (tid == 0) {
        float tot = 0.f;
#pragma unroll
        for (int i = 0; i < 8; i++) tot += red[i];
        atomicAdd(&g_scores[pidx], tot);
    }
}

// ---------------- k6: softmax over 3 scores + weighted combine ----------------
__global__ __launch_bounds__(256) void k6_out(float* __restrict__ out) {
    __shared__ float w[NP];
    if (threadIdx.x == 0) {
        float s0 = g_scores[0] * (1.f / NN);
        float s1 = g_scores[1] * (1.f / NN);
        float s2 = g_scores[2] * (1.f / NN);
        float mx = fmaxf(s0, fmaxf(s1, s2));
        float e0 = expf(s0 - mx), e1 = expf(s1 - mx), e2 = expf(s2 - mx);
        float inv = 1.f / (e0 + e1 + e2);
        w[0] = e0 * inv; w[1] = e1 * inv; w[2] = e2 * inv;
    }
    __syncthreads();
    size_t i = (size_t)blockIdx.x * blockDim.x + threadIdx.x;
    const size_t stride = (size_t)NN * 512;
    out[i] = w[0] * g_m[i] + w[1] * g_m[stride + i] + w[2] * g_m[2 * stride + i];
}

// ---------------- launch ----------------
extern "C" void kernel_launch(void* const* d_in, const int* in_sizes, int n_in,
                              void* d_out, int out_size) {
    const float* x    = (const float*)d_in[0];
    const float* adjs = (const float*)d_in[1];
    const float* Wn   = (const float*)d_in[2];
    const float* an   = (const float*)d_in[3];
    const float* Wsem = (const float*)d_in[4];
    const float* bsem = (const float*)d_in[5];
    const float* qsem = (const float*)d_in[6];
    float* out = (float*)d_out;

    k0_init<<<1, 32>>>();
    k1_node_gemm<<<dim3(NN / 64, PH), 256>>>(x, Wn);
    k2_sd<<<(PH * NN) / 8, 256>>>(an);
    k3_attn<<<dim3(NN / 64, PH), 128>>>(adjs);
    k4_sem<<<(NP * NN) / 32, 256>>>(Wsem, bsem, qsem);
    k6_out<<<(NN * 512) / 256, 256>>>(out);
}

// round 5
// speedup vs baseline: 1.2764x; 1.2764x over previous
#include <cuda_runtime.h>
#include <cuda_bf16.h>
#include <mma.h>
#include <math.h>
#include <stdint.h>
#include <string.h>

using namespace nvcuda;

#define NN     2048
#define NFEAT  512
#define NHID   128
#define NHEADS 4
#define NP     3
#define PH     (NP*NHEADS)
#define ALPHA  0.2f

// ---------------- device scratch ----------------
__device__ float g_m[NP * NN * (NHEADS*NHID)];                  // 12.6 MB
__device__ __align__(16) __nv_bfloat16 g_hThi[PH * NHID * NN];  // hT[ph][d][n] hi
__device__ __align__(16) __nv_bfloat16 g_hTlo[PH * NHID * NN];  // lo part
__device__ float4  g_sE4[PH * NN];     // (s, e^s, e^{as}, 0) per row n
__device__ float4  g_dE4[PH * NN];     // (d, e^d, e^{ad}, 0) per col m
__device__ uint32_t g_maskN[NP * NN * (NN/32)];
__device__ float g_scores[NP];

static __device__ __forceinline__ uint32_t b2u(__nv_bfloat162 h) {
    uint32_t u; memcpy(&u, &h, 4); return u;
}

// ---------------- k0 ----------------
__global__ void k0_init() { if (threadIdx.x < NP) g_scores[threadIdx.x] = 0.f; }

// ---------------- k_pack: adjacency -> bitmask ----------------
__global__ __launch_bounds__(256) void k_pack(const float* __restrict__ adjs) {
    int g = blockIdx.x * 8 + (threadIdx.x >> 5);    // [p][n][word]
    int lane = threadIdx.x & 31;
    float v = adjs[(size_t)g * 32 + lane];
    uint32_t b = __ballot_sync(0xffffffffu, v > 0.f);
    if (lane == 0) g_maskN[g] = b;
}

// ---------------- k1: node GEMM + hT(bf16 hi/lo) + s/d exps ----------------
__global__ __launch_bounds__(256) void k1_node(const float* __restrict__ x,
                                               const float* __restrict__ Wn,
                                               const float* __restrict__ an) {
    __shared__ float xs[64][33];
    __shared__ float ws[32 * 128];
    int ph   = blockIdx.y;
    int row0 = blockIdx.x * 64;
    const float* W = Wn + (size_t)ph * NFEAT * NHID;
    int tid = threadIdx.x;
    int rg = tid >> 4;
    int cg = tid & 15;

    float acc[4][8];
#pragma unroll
    for (int r = 0; r < 4; r++)
#pragma unroll
        for (int c = 0; c < 8; c++) acc[r][c] = 0.f;

    for (int k0 = 0; k0 < NFEAT; k0 += 32) {
        for (int i = tid; i < 64 * 32; i += 256)
            xs[i >> 5][i & 31] = x[(size_t)(row0 + (i >> 5)) * NFEAT + k0 + (i & 31)];
        for (int i = tid * 4; i < 32 * 128; i += 1024)
            *(float4*)&ws[i] = *(const float4*)&W[(size_t)k0 * 128 + i];
        __syncthreads();
#pragma unroll
        for (int k = 0; k < 32; k++) {
            float xv[4];
#pragma unroll
            for (int r = 0; r < 4; r++) xv[r] = xs[rg * 4 + r][k];
            float4 w0 = *(float4*)&ws[k * 128 + cg * 8];
            float4 w1 = *(float4*)&ws[k * 128 + cg * 8 + 4];
            float wv[8] = {w0.x, w0.y, w0.z, w0.w, w1.x, w1.y, w1.z, w1.w};
#pragma unroll
            for (int r = 0; r < 4; r++)
#pragma unroll
                for (int c = 0; c < 8; c++) acc[r][c] += xv[r] * wv[c];
        }
        __syncthreads();
    }

    const float* a = an + (size_t)ph * 2 * NHID;
    float asv[8], adv[8];
#pragma unroll
    for (int c = 0; c < 8; c++) { asv[c] = a[cg * 8 + c]; adv[c] = a[NHID + cg * 8 + c]; }

    float* red_s = &xs[0][0];   // [64][16]
    float* red_d = ws;          // [64][16]
#pragma unroll
    for (int r = 0; r < 4; r++) {
        float ps = 0.f, pd = 0.f;
#pragma unroll
        for (int c = 0; c < 8; c++) { ps += acc[r][c] * asv[c]; pd += acc[r][c] * adv[c]; }
        red_s[(rg * 4 + r) * 16 + cg] = ps;
        red_d[(rg * 4 + r) * 16 + cg] = pd;
    }

#pragma unroll
    for (int c = 0; c < 8; c++) {
        int d = cg * 8 + c;
        __nv_bfloat162 h01 = __float22bfloat162_rn(make_float2(acc[0][c], acc[1][c]));
        __nv_bfloat162 h23 = __float22bfloat162_rn(make_float2(acc[2][c], acc[3][c]));
        __nv_bfloat162 l01 = __float22bfloat162_rn(make_float2(acc[0][c] - __bfloat162float(h01.x),
                                                               acc[1][c] - __bfloat162float(h01.y)));
        __nv_bfloat162 l23 = __float22bfloat162_rn(make_float2(acc[2][c] - __bfloat162float(h23.x),
                                                               acc[3][c] - __bfloat162float(h23.y)));
        size_t off = ((size_t)ph * NHID + d) * NN + row0 + rg * 4;
        *(uint2*)((char*)g_hThi + off * 2) = make_uint2(b2u(h01), b2u(h23));
        *(uint2*)((char*)g_hTlo + off * 2) = make_uint2(b2u(l01), b2u(l23));
    }
    __syncthreads();
    if (tid < 64) {
        float s = 0.f, d = 0.f;
#pragma unroll
        for (int j = 0; j < 16; j++) { s += red_s[tid * 16 + j]; d += red_d[tid * 16 + j]; }
        int idx = ph * NN + row0 + tid;
        g_sE4[idx] = make_float4(s, expf(s), expf(ALPHA * s), 0.f);
        g_dE4[idx] = make_float4(d, expf(d), expf(ALPHA * d), 0.f);
    }
}

// ---------------- k3: WMMA attention ----------------
// smem map (bytes):
//   ash (A hi, 128 x 72 bf16)  @ 0      (18432)
//   asl (A lo)                 @ 18432  (18432)
//   bsh (B hi, 128 x 72 bf16)  @ 36864  (18432)
//   bsl (B lo)                 @ 55296  (18432)
//   csh (C, 128 x 132 f32) ALIASES 0..67584 (used only after MMA loop)
//   rsum [256] f32             @ 73728  (1024)
//   dE4  [64] float4           @ 74752  (1024)
#define LDA      72
#define LDC      132
#define OFF_AL   18432
#define OFF_BH   36864
#define OFF_BL   55296
#define OFF_ROW  73728
#define OFF_DE   74752
#define K3_SMEM_BYTES 75776

__global__ __launch_bounds__(256) void k3_attn_wmma() {
    extern __shared__ char sm[];
    __nv_bfloat16* ash = (__nv_bfloat16*)(sm);
    __nv_bfloat16* asl = (__nv_bfloat16*)(sm + OFF_AL);
    __nv_bfloat16* bsh = (__nv_bfloat16*)(sm + OFF_BH);
    __nv_bfloat16* bsl = (__nv_bfloat16*)(sm + OFF_BL);
    float*  csh  = (float*)(sm);
    float*  rsb  = (float*)(sm + OFF_ROW);
    float4* dEsh = (float4*)(sm + OFF_DE);

    int ph   = blockIdx.y;
    int p    = ph >> 2, head = ph & 3;
    int row0 = blockIdx.x * 128;
    int tid  = threadIdx.x;
    int warp = tid >> 5;
    int wr   = warp >> 1;     // 4 row groups of 32
    int wc   = warp & 1;      // 2 col groups of 64

    int r  = tid & 127;       // A-gen row
    int sh = tid >> 7;        // A-gen m half (32 each)
    float4 sE = g_sE4[ph * NN + row0 + r];
    const float s_r = sE.x, Es_r = sE.y, Eas_r = sE.z;
    float rs_local = 0.f;

    int dB = tid >> 1;        // B-load d row
    int hB = tid & 1;         // B-load m half

    wmma::fragment<wmma::accumulator, 16, 16, 16, float> c[2][4];
#pragma unroll
    for (int i = 0; i < 2; i++)
#pragma unroll
        for (int j = 0; j < 4; j++) wmma::fill_fragment(c[i][j], 0.f);

    for (int chk = 0; chk < 32; chk++) {
        int m0 = chk * 64;
        __syncthreads();   // previous compute done before tiles overwritten
        if (tid < 64) dEsh[tid] = g_dE4[ph * NN + m0 + tid];
        {   // B tile: hT hi/lo [128 d][64 m], padded stride LDA
            const uint4* srcH = (const uint4*)(g_hThi + ((size_t)ph * NHID + dB) * NN + m0 + hB * 32);
            const uint4* srcL = (const uint4*)(g_hTlo + ((size_t)ph * NHID + dB) * NN + m0 + hB * 32);
            uint4* dstH = (uint4*)(bsh + dB * LDA + hB * 32);
            uint4* dstL = (uint4*)(bsl + dB * LDA + hB * 32);
#pragma unroll
            for (int k = 0; k < 4; k++) { dstH[k] = srcH[k]; dstL[k] = srcL[k]; }
        }
        __syncthreads();   // dE staged

        {   // A tile: num row r, m in [m0+sh*32, +32)
            uint32_t mw = g_maskN[((size_t)p * NN + row0 + r) * 64 + chk * 2 + sh];
#pragma unroll
            for (int g4 = 0; g4 < 4; g4++) {
                float v[8];
#pragma unroll
                for (int j = 0; j < 8; j++) {
                    float4 q = dEsh[sh * 32 + g4 * 8 + j];
                    float t = s_r + q.x;
                    float w = (t > 0.f) ? (Es_r * q.y) : (Eas_r * q.z);
                    v[j] = ((mw >> (g4 * 8 + j)) & 1u) ? w : 0.f;
                    rs_local += v[j];
                }
                uint32_t hw[4], lw[4];
#pragma unroll
                for (int jj = 0; jj < 4; jj++) {
                    __nv_bfloat162 h2 = __float22bfloat162_rn(make_float2(v[2*jj], v[2*jj+1]));
                    __nv_bfloat162 l2 = __float22bfloat162_rn(
                        make_float2(v[2*jj]   - __bfloat162float(h2.x),
                                    v[2*jj+1] - __bfloat162float(h2.y)));
                    hw[jj] = b2u(h2); lw[jj] = b2u(l2);
                }
                *(uint4*)(ash + r * LDA + sh * 32 + g4 * 8) = make_uint4(hw[0], hw[1], hw[2], hw[3]);
                *(uint4*)(asl + r * LDA + sh * 32 + g4 * 8) = make_uint4(lw[0], lw[1], lw[2], lw[3]);
            }
        }
        __syncthreads();   // tiles ready

        // compute: 4 k-steps x (2 x 4 subtiles) x 3 split products
#pragma unroll
        for (int ks = 0; ks < 4; ks++) {
            int kk = ks * 16;
            wmma::fragment<wmma::matrix_a, 16, 16, 16, __nv_bfloat16, wmma::row_major> ah[2], al[2];
            wmma::fragment<wmma::matrix_b, 16, 16, 16, __nv_bfloat16, wmma::col_major> bh[4], bl[4];
#pragma unroll
            for (int i = 0; i < 2; i++) {
                wmma::load_matrix_sync(ah[i], ash + (wr * 32 + i * 16) * LDA + kk, LDA);
                wmma::load_matrix_sync(al[i], asl + (wr * 32 + i * 16) * LDA + kk, LDA);
            }
#pragma unroll
            for (int j = 0; j < 4; j++) {
                wmma::load_matrix_sync(bh[j], bsh + (wc * 64 + j * 16) * LDA + kk, LDA);
                wmma::load_matrix_sync(bl[j], bsl + (wc * 64 + j * 16) * LDA + kk, LDA);
            }
#pragma unroll
            for (int i = 0; i < 2; i++)
#pragma unroll
                for (int j = 0; j < 4; j++) {
                    wmma::mma_sync(c[i][j], ah[i], bh[j], c[i][j]);
                    wmma::mma_sync(c[i][j], ah[i], bl[j], c[i][j]);
                    wmma::mma_sync(c[i][j], al[i], bh[j], c[i][j]);
                }
        }
    }

    rsb[tid] = rs_local;
    __syncthreads();   // all compute done; rowsums visible; safe to alias C over A/B

#pragma unroll
    for (int i = 0; i < 2; i++)
#pragma unroll
        for (int j = 0; j < 4; j++)
            wmma::store_matrix_sync(csh + (wr * 32 + i * 16) * LDC + wc * 64 + j * 16,
                                    c[i][j], LDC, wmma::mem_row_major);
    __syncthreads();

    // epilogue: 2 threads per row, 64 cols each
    {
        int rr  = tid & 127;
        int chf = tid >> 7;
        float rsum = rsb[rr] + rsb[128 + rr];
        float inv = (rsum > 0.f) ? (1.f / rsum) : 0.f;
        const float* src = csh + rr * LDC + chf * 64;
        float* dst = g_m + ((size_t)p * NN + row0 + rr) * (NHEADS * NHID) + head * NHID + chf * 64;
#pragma unroll
        for (int cc = 0; cc < 64; cc += 4) {
            float f0 = src[cc]   * inv;
            float f1 = src[cc+1] * inv;
            float f2 = src[cc+2] * inv;
            float f3 = src[cc+3] * inv;
            f0 = (f0 > 0.f) ? f0 : expm1f(f0);
            f1 = (f1 > 0.f) ? f1 : expm1f(f1);
            f2 = (f2 > 0.f) ? f2 : expm1f(f2);
            f3 = (f3 > 0.f) ? f3 : expm1f(f3);
            *(float4*)(dst + cc) = make_float4(f0, f1, f2, f3);
        }
    }
}

// ---------------- k4: semantic scores ----------------
__global__ __launch_bounds__(256) void k4_sem(const float* __restrict__ Wsem,
                                              const float* __restrict__ bsem,
                                              const float* __restrict__ qsem) {
    __shared__ float msh[32][65];
    __shared__ float wsh[64 * 128];
    __shared__ float red[8];
    int row0 = blockIdx.x * 32;
    int pidx = row0 / NN;
    int tid = threadIdx.x;
    int rg = tid >> 5;
    int cg = tid & 31;

    float acc[4][4];
#pragma unroll
    for (int r = 0; r < 4; r++)
#pragma unroll
        for (int c = 0; c < 4; c++) acc[r][c] = 0.f;

    for (int k0 = 0; k0 < 512; k0 += 64) {
        for (int i = tid; i < 32 * 64; i += 256)
            msh[i >> 6][i & 63] = g_m[(size_t)(row0 + (i >> 6)) * 512 + k0 + (i & 63)];
        for (int i = tid * 4; i < 64 * 128; i += 1024)
            *(float4*)&wsh[i] = *(const float4*)&Wsem[(size_t)k0 * 128 + i];
        __syncthreads();
#pragma unroll
        for (int k = 0; k < 64; k++) {
            float mv[4];
#pragma unroll
            for (int r = 0; r < 4; r++) mv[r] = msh[rg * 4 + r][k];
            float4 wv = *(float4*)&wsh[k * 128 + cg * 4];
            float wva[4] = {wv.x, wv.y, wv.z, wv.w};
#pragma unroll
            for (int r = 0; r < 4; r++)
#pragma unroll
                for (int c = 0; c < 4; c++) acc[r][c] += mv[r] * wva[c];
        }
        __syncthreads();
    }
    float part = 0.f;
#pragma unroll
    for (int c = 0; c < 4; c++) {
        int col = cg * 4 + c;
        float b = bsem[col], q = qsem[col];
#pragma unroll
        for (int r = 0; r < 4; r++)
            part += tanhf(acc[r][c] + b) * q;
    }
#pragma unroll
    for (int off = 16; off; off >>= 1)
        part += __shfl_xor_sync(0xffffffffu, part, off);
    if ((tid & 31) == 0) red[tid >> 5] = part;
    __syncthreads();
    if (tid == 0) {
        float tot = 0.f;
#pragma unroll
        for (int i = 0; i < 8; i++) tot += red[i];
        atomicAdd(&g_scores[pidx], tot);
    }
}

// ---------------- k6: softmax over 3 + combine ----------------
__global__ __launch_bounds__(256) void k6_out(float* __restrict__ out) {
    __shared__ float w[NP];
    if (threadIdx.x == 0) {
        float s0 = g_scores[0] * (1.f / NN);
        float s1 = g_scores[1] * (1.f / NN);
        float s2 = g_scores[2] * (1.f / NN);
        float mx = fmaxf(s0, fmaxf(s1, s2));
        float e0 = expf(s0 - mx), e1 = expf(s1 - mx), e2 = expf(s2 - mx);
        float inv = 1.f / (e0 + e1 + e2);
        w[0] = e0 * inv; w[1] = e1 * inv; w[2] = e2 * inv;
    }
    __syncthreads();
    size_t i = (size_t)blockIdx.x * blockDim.x + threadIdx.x;
    const size_t stride = (size_t)NN * 512;
    out[i] = w[0] * g_m[i] + w[1] * g_m[stride + i] + w[2] * g_m[2 * stride + i];
}

// ---------------- launch ----------------
extern "C" void kernel_launch(void* const* d_in, const int* in_sizes, int n_in,
                              void* d_out, int out_size) {
    const float* x    = (const float*)d_in[0];
    const float* adjs = (const float*)d_in[1];
    const float* Wn   = (const float*)d_in[2];
    const float* an   = (const float*)d_in[3];
    const float* Wsem = (const float*)d_in[4];
    const float* bsem = (const float*)d_in[5];
    const float* qsem = (const float*)d_in[6];
    float* out = (float*)d_out;

    cudaFuncSetAttribute(k3_attn_wmma, cudaFuncAttributeMaxDynamicSharedMemorySize, K3_SMEM_BYTES);

    k0_init<<<1, 32>>>();
    k_pack<<<NP * NN * 64 / 8, 256>>>(adjs);
    k1_node<<<dim3(NN / 64, PH), 256>>>(x, Wn, an);
    k3_attn_wmma<<<dim3(NN / 128, PH), 256, K3_SMEM_BYTES>>>();
    k4_sem<<<(NP * NN) / 32, 256>>>(Wsem, bsem, qsem);
    k6_out<<<(NN * 512) / 256, 256>>>(out);
}

// round 6
// speedup vs baseline: 1.5806x; 1.2383x over previous
#include <cuda_runtime.h>
#include <cuda_bf16.h>
#include <mma.h>
#include <math.h>
#include <stdint.h>
#include <string.h>

using namespace nvcuda;

#define NN     2048
#define NFEAT  512
#define NHID   128
#define NHEADS 4
#define NP     3
#define PH     (NP*NHEADS)
#define ALPHA  0.2f

// ---------------- device scratch ----------------
__device__ float g_m[NP * NN * (NHEADS*NHID)];                  // 12.6 MB
__device__ __align__(16) __nv_bfloat16 g_hThi[PH * NHID * NN];  // hT[ph][d][n] hi
__device__ __align__(16) __nv_bfloat16 g_hTlo[PH * NHID * NN];  // lo
__device__ __align__(16) __nv_bfloat16 g_xhi[NN * NFEAT];       // x split
__device__ __align__(16) __nv_bfloat16 g_xlo[NN * NFEAT];
__device__ __align__(16) __nv_bfloat16 g_Whi[PH * NFEAT * NHID];// W_node split
__device__ __align__(16) __nv_bfloat16 g_Wlo[PH * NFEAT * NHID];
__device__ float4  g_sE4[PH * NN];     // (s, e^s, e^{as}, 0) per row n
__device__ float4  g_dE4[PH * NN];     // (d, e^d, e^{ad}, 0) per col m
__device__ uint32_t g_maskN[NP * NN * (NN/32)];
__device__ float g_scores[NP];

static __device__ __forceinline__ uint32_t b2u(__nv_bfloat162 h) {
    uint32_t u; memcpy(&u, &h, 4); return u;
}

// ---------------- k0 ----------------
__global__ void k0_init() { if (threadIdx.x < NP) g_scores[threadIdx.x] = 0.f; }

// ---------------- k_split: fp32 -> bf16 hi/lo for x and W_node ----------------
#define NXE (NN * NFEAT)
#define NWE (PH * NFEAT * NHID)
__global__ __launch_bounds__(256) void k_split(const float* __restrict__ x,
                                               const float* __restrict__ Wn) {
    int i = blockIdx.x * 256 + threadIdx.x;
    if (i < NXE) {
        float v = x[i];
        __nv_bfloat16 h = __float2bfloat16_rn(v);
        g_xhi[i] = h;
        g_xlo[i] = __float2bfloat16_rn(v - __bfloat162float(h));
    }
    int j = i - NXE;
    if (j >= 0 && j < NWE) {
        float v = Wn[j];
        __nv_bfloat16 h = __float2bfloat16_rn(v);
        g_Whi[j] = h;
        g_Wlo[j] = __float2bfloat16_rn(v - __bfloat162float(h));
    }
}

// ---------------- k_pack: adjacency -> bitmask ----------------
__global__ __launch_bounds__(256) void k_pack(const float* __restrict__ adjs) {
    int g = blockIdx.x * 8 + (threadIdx.x >> 5);    // [p][n][word]
    int lane = threadIdx.x & 31;
    float v = adjs[(size_t)g * 32 + lane];
    uint32_t b = __ballot_sync(0xffffffffu, v > 0.f);
    if (lane == 0) g_maskN[g] = b;
}

// ---------------- k1: WMMA node GEMM + hT(bf16 hi/lo) + s/d exps ----------------
// output tile 128 rows x 128 dims, K = 512 in chunks of 64.
// smem: ash/asl [128][72] bf16, bsh/bsl [64][136] bf16, C [128][132] f32 aliased,
//       a_node stage [256] f32, red_s/red_d [256] f32 each.
#define K1_LDA   72
#define K1_LDB   136
#define K1_LDC   132
#define K1_OFF_AL 18432
#define K1_OFF_BH 36864
#define K1_OFF_BL 54272
#define K1_OFF_AN 73728
#define K1_OFF_RS 74752
#define K1_OFF_RD 75776
#define K1_SMEM_BYTES 76800

__global__ __launch_bounds__(256, 2) void k1_node_wmma(const float* __restrict__ an) {
    extern __shared__ char sm[];
    __nv_bfloat16* ash = (__nv_bfloat16*)(sm);
    __nv_bfloat16* asl = (__nv_bfloat16*)(sm + K1_OFF_AL);
    __nv_bfloat16* bsh = (__nv_bfloat16*)(sm + K1_OFF_BH);
    __nv_bfloat16* bsl = (__nv_bfloat16*)(sm + K1_OFF_BL);
    float* csh   = (float*)(sm);
    float* a_sh  = (float*)(sm + K1_OFF_AN);
    float* red_s = (float*)(sm + K1_OFF_RS);
    float* red_d = (float*)(sm + K1_OFF_RD);

    int ph   = blockIdx.y;
    int row0 = blockIdx.x * 128;
    int tid  = threadIdx.x;
    int warp = tid >> 5;
    int wr   = warp >> 1;     // 4 row groups of 32
    int wc   = warp & 1;      // 2 col groups of 64

    wmma::fragment<wmma::accumulator, 16, 16, 16, float> c[2][4];
#pragma unroll
    for (int i = 0; i < 2; i++)
#pragma unroll
        for (int j = 0; j < 4; j++) wmma::fill_fragment(c[i][j], 0.f);

    int rA = tid >> 1, hA = tid & 1;    // A load: row, k-half(32)
    int rB = tid >> 2, qB = tid & 3;    // B load: k row, n-quarter(32)

    for (int k0 = 0; k0 < NFEAT; k0 += 64) {
        __syncthreads();
        {   // A tile: x rows [row0..+128), k [k0..+64)
            const uint4* srcH = (const uint4*)(g_xhi + (size_t)(row0 + rA) * NFEAT + k0 + hA * 32);
            const uint4* srcL = (const uint4*)(g_xlo + (size_t)(row0 + rA) * NFEAT + k0 + hA * 32);
            uint4* dH = (uint4*)(ash + rA * K1_LDA + hA * 32);
            uint4* dL = (uint4*)(asl + rA * K1_LDA + hA * 32);
#pragma unroll
            for (int k = 0; k < 4; k++) { dH[k] = srcH[k]; dL[k] = srcL[k]; }
        }
        {   // B tile: W [k0..+64)[0..128)
            const uint4* srcH = (const uint4*)(g_Whi + (size_t)ph * NFEAT * NHID + (size_t)(k0 + rB) * NHID + qB * 32);
            const uint4* srcL = (const uint4*)(g_Wlo + (size_t)ph * NFEAT * NHID + (size_t)(k0 + rB) * NHID + qB * 32);
            uint4* dH = (uint4*)(bsh + rB * K1_LDB + qB * 32);
            uint4* dL = (uint4*)(bsl + rB * K1_LDB + qB * 32);
#pragma unroll
            for (int k = 0; k < 4; k++) { dH[k] = srcH[k]; dL[k] = srcL[k]; }
        }
        __syncthreads();

#pragma unroll
        for (int ks = 0; ks < 4; ks++) {
            int kk = ks * 16;
            wmma::fragment<wmma::matrix_a, 16, 16, 16, __nv_bfloat16, wmma::row_major> ah[2], al[2];
            wmma::fragment<wmma::matrix_b, 16, 16, 16, __nv_bfloat16, wmma::row_major> bh[4], bl[4];
#pragma unroll
            for (int i = 0; i < 2; i++) {
                wmma::load_matrix_sync(ah[i], ash + (wr * 32 + i * 16) * K1_LDA + kk, K1_LDA);
                wmma::load_matrix_sync(al[i], asl + (wr * 32 + i * 16) * K1_LDA + kk, K1_LDA);
            }
#pragma unroll
            for (int j = 0; j < 4; j++) {
                wmma::load_matrix_sync(bh[j], bsh + kk * K1_LDB + wc * 64 + j * 16, K1_LDB);
                wmma::load_matrix_sync(bl[j], bsl + kk * K1_LDB + wc * 64 + j * 16, K1_LDB);
            }
#pragma unroll
            for (int i = 0; i < 2; i++)
#pragma unroll
                for (int j = 0; j < 4; j++) {
                    wmma::mma_sync(c[i][j], ah[i], bh[j], c[i][j]);
                    wmma::mma_sync(c[i][j], ah[i], bl[j], c[i][j]);
                    wmma::mma_sync(c[i][j], al[i], bh[j], c[i][j]);
                }
        }
    }

    __syncthreads();    // done with A/B smem; alias C over it
    a_sh[tid] = an[(size_t)ph * 2 * NHID + tid];
#pragma unroll
    for (int i = 0; i < 2; i++)
#pragma unroll
        for (int j = 0; j < 4; j++)
            wmma::store_matrix_sync(csh + (wr * 32 + i * 16) * K1_LDC + wc * 64 + j * 16,
                                    c[i][j], K1_LDC, wmma::mem_row_major);
    __syncthreads();

    // s/d partial dots: 2 threads per row (halves of d)
    {
        int r = tid & 127, hf = tid >> 7;
        float ps = 0.f, pd = 0.f;
        const float* row = csh + r * K1_LDC + hf * 64;
#pragma unroll
        for (int i = 0; i < 64; i++) {
            float v = row[i];
            ps += v * a_sh[hf * 64 + i];
            pd += v * a_sh[NHID + hf * 64 + i];
        }
        red_s[hf * 128 + r] = ps;
        red_d[hf * 128 + r] = pd;
    }

    // hT hi/lo: thread (d, half-of-rows) writes 64 n values for dim d
    {
        int d = tid & 127, hf = tid >> 7;
        __nv_bfloat16* dstH = g_hThi + ((size_t)ph * NHID + d) * NN + row0 + hf * 64;
        __nv_bfloat16* dstL = g_hTlo + ((size_t)ph * NHID + d) * NN + row0 + hf * 64;
#pragma unroll
        for (int i = 0; i < 64; i += 4) {
            float v0 = csh[(hf * 64 + i    ) * K1_LDC + d];
            float v1 = csh[(hf * 64 + i + 1) * K1_LDC + d];
            float v2 = csh[(hf * 64 + i + 2) * K1_LDC + d];
            float v3 = csh[(hf * 64 + i + 3) * K1_LDC + d];
            __nv_bfloat162 h01 = __float22bfloat162_rn(make_float2(v0, v1));
            __nv_bfloat162 h23 = __float22bfloat162_rn(make_float2(v2, v3));
            __nv_bfloat162 l01 = __float22bfloat162_rn(make_float2(v0 - __bfloat162float(h01.x),
                                                                   v1 - __bfloat162float(h01.y)));
            __nv_bfloat162 l23 = __float22bfloat162_rn(make_float2(v2 - __bfloat162float(h23.x),
                                                                   v3 - __bfloat162float(h23.y)));
            *(uint2*)(dstH + i) = make_uint2(b2u(h01), b2u(h23));
            *(uint2*)(dstL + i) = make_uint2(b2u(l01), b2u(l23));
        }
    }
    __syncthreads();
    if (tid < 128) {
        float s = red_s[tid] + red_s[128 + tid];
        float d = red_d[tid] + red_d[128 + tid];
        int idx = ph * NN + row0 + tid;
        g_sE4[idx] = make_float4(s, expf(s), expf(ALPHA * s), 0.f);
        g_dE4[idx] = make_float4(d, expf(d), expf(ALPHA * d), 0.f);
    }
}

// ---------------- k3: WMMA attention ----------------
#define LDA      72
#define LDC      132
#define OFF_AL   18432
#define OFF_BH   36864
#define OFF_BL   55296
#define OFF_ROW  73728
#define OFF_DE   74752
#define K3_SMEM_BYTES 75776

__global__ __launch_bounds__(256, 2) void k3_attn_wmma() {
    extern __shared__ char sm[];
    __nv_bfloat16* ash = (__nv_bfloat16*)(sm);
    __nv_bfloat16* asl = (__nv_bfloat16*)(sm + OFF_AL);
    __nv_bfloat16* bsh = (__nv_bfloat16*)(sm + OFF_BH);
    __nv_bfloat16* bsl = (__nv_bfloat16*)(sm + OFF_BL);
    float*  csh  = (float*)(sm);
    float*  rsb  = (float*)(sm + OFF_ROW);
    float4* dEsh = (float4*)(sm + OFF_DE);

    int ph   = blockIdx.y;
    int p    = ph >> 2, head = ph & 3;
    int row0 = blockIdx.x * 128;
    int tid  = threadIdx.x;
    int warp = tid >> 5;
    int wr   = warp >> 1;
    int wc   = warp & 1;

    int r  = tid & 127;
    int sh = tid >> 7;
    float4 sE = g_sE4[ph * NN + row0 + r];
    const float s_r = sE.x, Es_r = sE.y, Eas_r = sE.z;
    float rs_local = 0.f;

    int dB = tid >> 1;
    int hB = tid & 1;

    wmma::fragment<wmma::accumulator, 16, 16, 16, float> c[2][4];
#pragma unroll
    for (int i = 0; i < 2; i++)
#pragma unroll
        for (int j = 0; j < 4; j++) wmma::fill_fragment(c[i][j], 0.f);

    for (int chk = 0; chk < 32; chk++) {
        int m0 = chk * 64;
        __syncthreads();
        if (tid < 64) dEsh[tid] = g_dE4[ph * NN + m0 + tid];
        {
            const uint4* srcH = (const uint4*)(g_hThi + ((size_t)ph * NHID + dB) * NN + m0 + hB * 32);
            const uint4* srcL = (const uint4*)(g_hTlo + ((size_t)ph * NHID + dB) * NN + m0 + hB * 32);
            uint4* dstH = (uint4*)(bsh + dB * LDA + hB * 32);
            uint4* dstL = (uint4*)(bsl + dB * LDA + hB * 32);
#pragma unroll
            for (int k = 0; k < 4; k++) { dstH[k] = srcH[k]; dstL[k] = srcL[k]; }
        }
        __syncthreads();

        {
            uint32_t mw = g_maskN[((size_t)p * NN + row0 + r) * 64 + chk * 2 + sh];
#pragma unroll
            for (int g4 = 0; g4 < 4; g4++) {
                float v[8];
#pragma unroll
                for (int j = 0; j < 8; j++) {
                    float4 q = dEsh[sh * 32 + g4 * 8 + j];
                    float t = s_r + q.x;
                    float w = (t > 0.f) ? (Es_r * q.y) : (Eas_r * q.z);
                    v[j] = ((mw >> (g4 * 8 + j)) & 1u) ? w : 0.f;
                    rs_local += v[j];
                }
                uint32_t hw[4], lw[4];
#pragma unroll
                for (int jj = 0; jj < 4; jj++) {
                    __nv_bfloat162 h2 = __float22bfloat162_rn(make_float2(v[2*jj], v[2*jj+1]));
                    __nv_bfloat162 l2 = __float22bfloat162_rn(
                        make_float2(v[2*jj]   - __bfloat162float(h2.x),
                                    v[2*jj+1] - __bfloat162float(h2.y)));
                    hw[jj] = b2u(h2); lw[jj] = b2u(l2);
                }
                *(uint4*)(ash + r * LDA + sh * 32 + g4 * 8) = make_uint4(hw[0], hw[1], hw[2], hw[3]);
                *(uint4*)(asl + r * LDA + sh * 32 + g4 * 8) = make_uint4(lw[0], lw[1], lw[2], lw[3]);
            }
        }
        __syncthreads();

#pragma unroll
        for (int ks = 0; ks < 4; ks++) {
            int kk = ks * 16;
            wmma::fragment<wmma::matrix_a, 16, 16, 16, __nv_bfloat16, wmma::row_major> ah[2], al[2];
            wmma::fragment<wmma::matrix_b, 16, 16, 16, __nv_bfloat16, wmma::col_major> bh[4], bl[4];
#pragma unroll
            for (int i = 0; i < 2; i++) {
                wmma::load_matrix_sync(ah[i], ash + (wr * 32 + i * 16) * LDA + kk, LDA);
                wmma::load_matrix_sync(al[i], asl + (wr * 32 + i * 16) * LDA + kk, LDA);
            }
#pragma unroll
            for (int j = 0; j < 4; j++) {
                wmma::load_matrix_sync(bh[j], bsh + (wc * 64 + j * 16) * LDA + kk, LDA);
                wmma::load_matrix_sync(bl[j], bsl + (wc * 64 + j * 16) * LDA + kk, LDA);
            }
#pragma unroll
            for (int i = 0; i < 2; i++)
#pragma unroll
                for (int j = 0; j < 4; j++) {
                    wmma::mma_sync(c[i][j], ah[i], bh[j], c[i][j]);
                    wmma::mma_sync(c[i][j], ah[i], bl[j], c[i][j]);
                    wmma::mma_sync(c[i][j], al[i], bh[j], c[i][j]);
                }
        }
    }

    rsb[tid] = rs_local;
    __syncthreads();

#pragma unroll
    for (int i = 0; i < 2; i++)
#pragma unroll
        for (int j = 0; j < 4; j++)
            wmma::store_matrix_sync(csh + (wr * 32 + i * 16) * LDC + wc * 64 + j * 16,
                                    c[i][j], LDC, wmma::mem_row_major);
    __syncthreads();

    {
        int rr  = tid & 127;
        int chf = tid >> 7;
        float rsum = rsb[rr] + rsb[128 + rr];
        float inv = (rsum > 0.f) ? (1.f / rsum) : 0.f;
        const float* src = csh + rr * LDC + chf * 64;
        float* dst = g_m + ((size_t)p * NN + row0 + rr) * (NHEADS * NHID) + head * NHID + chf * 64;
#pragma unroll
        for (int cc = 0; cc < 64; cc += 4) {
            float f0 = src[cc]   * inv;
            float f1 = src[cc+1] * inv;
            float f2 = src[cc+2] * inv;
            float f3 = src[cc+3] * inv;
            f0 = (f0 > 0.f) ? f0 : expm1f(f0);
            f1 = (f1 > 0.f) ? f1 : expm1f(f1);
            f2 = (f2 > 0.f) ? f2 : expm1f(f2);
            f3 = (f3 > 0.f) ? f3 : expm1f(f3);
            *(float4*)(dst + cc) = make_float4(f0, f1, f2, f3);
        }
    }
}

// ---------------- k4: semantic scores ----------------
__global__ __launch_bounds__(256) void k4_sem(const float* __restrict__ Wsem,
                                              const float* __restrict__ bsem,
                                              const float* __restrict__ qsem) {
    __shared__ float msh[32][65];
    __shared__ float wsh[64 * 128];
    __shared__ float red[8];
    int row0 = blockIdx.x * 32;
    int pidx = row0 / NN;
    int tid = threadIdx.x;
    int rg = tid >> 5;
    int cg = tid & 31;

    float acc[4][4];
#pragma unroll
    for (int r = 0; r < 4; r++)
#pragma unroll
        for (int c = 0; c < 4; c++) acc[r][c] = 0.f;

    for (int k0 = 0; k0 < 512; k0 += 64) {
        for (int i = tid; i < 32 * 64; i += 256)
            msh[i >> 6][i & 63] = g_m[(size_t)(row0 + (i >> 6)) * 512 + k0 + (i & 63)];
        for (int i = tid * 4; i < 64 * 128; i += 1024)
            *(float4*)&wsh[i] = *(const float4*)&Wsem[(size_t)k0 * 128 + i];
        __syncthreads();
#pragma unroll
        for (int k = 0; k < 64; k++) {
            float mv[4];
#pragma unroll
            for (int r = 0; r < 4; r++) mv[r] = msh[rg * 4 + r][k];
            float4 wv = *(float4*)&wsh[k * 128 + cg * 4];
            float wva[4] = {wv.x, wv.y, wv.z, wv.w};
#pragma unroll
            for (int r = 0; r < 4; r++)
#pragma unroll
                for (int c = 0; c < 4; c++) acc[r][c] += mv[r] * wva[c];
        }
        __syncthreads();
    }
    float part = 0.f;
#pragma unroll
    for (int c = 0; c < 4; c++) {
        int col = cg * 4 + c;
        float b = bsem[col], q = qsem[col];
#pragma unroll
        for (int r = 0; r < 4; r++)
            part += tanhf(acc[r][c] + b) * q;
    }
#pragma unroll
    for (int off = 16; off; off >>= 1)
        part += __shfl_xor_sync(0xffffffffu, part, off);
    if ((tid & 31) == 0) red[tid >> 5] = part;
    __syncthreads();
    if (tid == 0) {
        float tot = 0.f;
#pragma unroll
        for (int i = 0; i < 8; i++) tot += red[i];
        atomicAdd(&g_scores[pidx], tot);
    }
}

// ---------------- k6: softmax over 3 + combine ----------------
__global__ __launch_bounds__(256) void k6_out(float* __restrict__ out) {
    __shared__ float w[NP];
    if (threadIdx.x == 0) {
        float s0 = g_scores[0] * (1.f / NN);
        float s1 = g_scores[1] * (1.f / NN);
        float s2 = g_scores[2] * (1.f / NN);
        float mx = fmaxf(s0, fmaxf(s1, s2));
        float e0 = expf(s0 - mx), e1 = expf(s1 - mx), e2 = expf(s2 - mx);
        float inv = 1.f / (e0 + e1 + e2);
        w[0] = e0 * inv; w[1] = e1 * inv; w[2] = e2 * inv;
    }
    __syncthreads();
    size_t i = (size_t)blockIdx.x * blockDim.x + threadIdx.x;
    const size_t stride = (size_t)NN * 512;
    out[i] = w[0] * g_m[i] + w[1] * g_m[stride + i] + w[2] * g_m[2 * stride + i];
}

// ---------------- launch ----------------
extern "C" void kernel_launch(void* const* d_in, const int* in_sizes, int n_in,
                              void* d_out, int out_size) {
    const float* x    = (const float*)d_in[0];
    const float* adjs = (const float*)d_in[1];
    const float* Wn   = (const float*)d_in[2];
    const float* an   = (const float*)d_in[3];
    const float* Wsem = (const float*)d_in[4];
    const float* bsem = (const float*)d_in[5];
    const float* qsem = (const float*)d_in[6];
    float* out = (float*)d_out;

    cudaFuncSetAttribute(k3_attn_wmma, cudaFuncAttributeMaxDynamicSharedMemorySize, K3_SMEM_BYTES);
    cudaFuncSetAttribute(k1_node_wmma, cudaFuncAttributeMaxDynamicSharedMemorySize, K1_SMEM_BYTES);

    k0_init<<<1, 32>>>();
    k_split<<<(NXE + NWE + 255) / 256, 256>>>(x, Wn);
    k_pack<<<NP * NN * 64 / 8, 256>>>(adjs);
    k1_node_wmma<<<dim3(NN / 128, PH), 256, K1_SMEM_BYTES>>>(an);
    k3_attn_wmma<<<dim3(NN / 128, PH), 256, K3_SMEM_BYTES>>>();
    k4_sem<<<(NP * NN) / 32, 256>>>(Wsem, bsem, qsem);
    k6_out<<<(NN * 512) / 256, 256>>>(out);
}